// round 14
// baseline (speedup 1.0000x reference)
#include <cuda_runtime.h>
#include <cuda_fp16.h>
#include <math.h>

#define NN 50000
#define NE 800000
#define DEPTH 4
#define NBLK 196   // (NN + 255) / 256

// ---------------- side stream for capture-time fork/join (created at static
// init, before any harness memory checkpoint; host-side resources only) ------
struct SideStream {
    cudaStream_t s;
    cudaEvent_t evFork, evJoin;
    SideStream() {
        cudaStreamCreate(&s);
        cudaEventCreateWithFlags(&evFork, cudaEventDisableTiming);
        cudaEventCreateWithFlags(&evJoin, cudaEventDisableTiming);
    }
};
static SideStream g_ss;

// ---------------- scratch (static device globals; no allocation) ----------------
__device__ float  g_X  [NN*64];   // node state (fp32)
__device__ __half g_XdH[NN*64];   // dis[i]*X[i] as fp16 (gather stream)
__device__ __half g_AH [NN*64];   // aggregated features as fp16 (MMA input)
__device__ __half g_XnH[NN*64];   // relu(conv(X)) as fp16
__device__ __half g_XGH[NN*64];   // relu(gate-conv(X)) as fp16 (gather stream)
__device__ __half g_Wt1[64*64];   // conv_w transposed fp16: [n][k]
__device__ __half g_Wt2[64*64];   // gg_w transposed fp16: [n][k]
__device__ __half g_WtD[64*64];   // dec_w transposed fp16: [n][k]
__device__ __half g_WtE[64*256];  // enc_w transposed fp16: [n][k]
__device__ float g_dis[NN];
__device__ int g_cnt_dst[NN];
__device__ int g_cnt_src[NN];
__device__ int g_rp_dst[NN+1];
__device__ int g_rp_src[NN+1];
__device__ int g_off_dst[NN];
__device__ int g_off_src[NN];
__device__ unsigned short g_col_src[NE];   // CSR by dst (16-bit node ids)
__device__ unsigned short g_col_dst[NE];   // CSR by src
__device__ unsigned g_desc[2][NBLK];       // decoupled-lookback descriptors

// ---------------- helpers ----------------
__device__ __forceinline__ float4 h4_to_f4(uint2 raw) {
    __half2 h0 = *reinterpret_cast<__half2*>(&raw.x);
    __half2 h1 = *reinterpret_cast<__half2*>(&raw.y);
    float2 f0 = __half22float2(h0);
    float2 f1 = __half22float2(h1);
    return make_float4(f0.x, f0.y, f1.x, f1.y);
}
__device__ __forceinline__ uint2 f4_to_h4(float4 v) {
    __half2 h0 = __floats2half2_rn(v.x, v.y);
    __half2 h1 = __floats2half2_rn(v.z, v.w);
    uint2 r;
    r.x = *reinterpret_cast<unsigned*>(&h0);
    r.y = *reinterpret_cast<unsigned*>(&h1);
    return r;
}
__device__ __forceinline__ void mma16816(float c[4],
    unsigned a0, unsigned a1, unsigned a2, unsigned a3,
    unsigned b0, unsigned b1)
{
    asm volatile(
        "mma.sync.aligned.m16n8k16.row.col.f32.f16.f16.f32 "
        "{%0,%1,%2,%3}, {%4,%5,%6,%7}, {%8,%9}, {%0,%1,%2,%3};"
        : "+f"(c[0]), "+f"(c[1]), "+f"(c[2]), "+f"(c[3])
        : "r"(a0), "r"(a1), "r"(a2), "r"(a3), "r"(b0), "r"(b1));
}

// inclusive block scan, 256 threads (8 warps)
__device__ __forceinline__ int block_incl_scan(int v, int* warpsums) {
    int lane = threadIdx.x & 31, wid = threadIdx.x >> 5;
    #pragma unroll
    for (int o = 1; o < 32; o <<= 1) {
        int u = __shfl_up_sync(0xffffffffu, v, o);
        if (lane >= o) v += u;
    }
    if (lane == 31) warpsums[wid] = v;
    __syncthreads();
    if (wid == 0) {
        int s = (lane < 8) ? warpsums[lane] : 0;
        #pragma unroll
        for (int o = 1; o < 8; o <<= 1) {
            int u = __shfl_up_sync(0xffffffffu, s, o);
            if (lane >= o) s += u;
        }
        if (lane < 8) warpsums[lane] = s;
    }
    __syncthreads();
    if (wid > 0) v += warpsums[wid - 1];
    return v;
}

// ---------------- prologue: zero counts/descriptors + convert weights ----------------
__global__ void k_pre(const float* __restrict__ w1, const float* __restrict__ w2,
                      const float* __restrict__ wd, const float* __restrict__ we) {
    int i = blockIdx.x * blockDim.x + threadIdx.x;
    if (i < NN) { g_cnt_dst[i] = 0; g_cnt_src[i] = 0; }
    if (i < NBLK) { g_desc[0][i] = 0u; g_desc[1][i] = 0u; }
    if (i < 4096) {
        int k = i >> 6, n = i & 63;
        g_Wt1[n * 64 + k] = __float2half(w1[i]);
        g_Wt2[n * 64 + k] = __float2half(w2[i]);
        g_WtD[n * 64 + k] = __float2half(wd[i]);
    }
    if (i < 16384) {
        int k = i >> 6, n = i & 63;
        g_WtE[n * 256 + k] = __float2half(we[i]);
    }
}

__global__ void k_count(const int* __restrict__ ei) {
    int i = blockIdx.x * blockDim.x + threadIdx.x;
    if (i < NE / 2) {
        int2 s = *(const int2*)&ei[2 * i];
        int2 d = *(const int2*)&ei[NE + 2 * i];
        atomicAdd(&g_cnt_dst[d.x], 1);
        atomicAdd(&g_cnt_dst[d.y], 1);
        atomicAdd(&g_cnt_src[s.x], 1);
        atomicAdd(&g_cnt_src[s.y], 1);
    }
}

// ---------------- single-pass scan with decoupled lookback ----------------
__global__ void __launch_bounds__(256) k_scan_one() {
    __shared__ int warpsums[8];
    __shared__ int s_prefix;
    int arr = blockIdx.y;
    const int* cnt = arr ? g_cnt_src : g_cnt_dst;
    int* rp  = arr ? g_rp_src  : g_rp_dst;
    int* off = arr ? g_off_src : g_off_dst;
    int blk = blockIdx.x;
    int i = blk * 256 + threadIdx.x;
    int v = (i < NN) ? cnt[i] : 0;
    int inc = block_incl_scan(v, warpsums);
    int lane = threadIdx.x & 31, wid = threadIdx.x >> 5;

    if (wid == 7) {
        int blockAgg = __shfl_sync(0xffffffffu, inc, 31);
        if (blk == 0) {
            if (lane == 31) {
                atomicExch(&g_desc[arr][0], (unsigned)blockAgg | 0x80000000u);
                s_prefix = 0;
            }
        } else {
            if (lane == 31)
                atomicExch(&g_desc[arr][blk], (unsigned)blockAgg | 0x40000000u);
            __syncwarp();
            int exc = 0;
            int base_j = blk - 1;
            while (true) {
                int j = base_j - (31 - lane);
                unsigned d;
                if (j >= 0) {
                    do { d = *((volatile unsigned*)&g_desc[arr][j]); }
                    while ((d & 0xC0000000u) == 0u);
                } else {
                    d = 0x80000000u;
                }
                unsigned pb = __ballot_sync(0xffffffffu, (d & 0x80000000u) != 0u);
                if (pb) {
                    int lp = 31 - __clz(pb);
                    int contrib = (lane >= lp) ? (int)(d & 0x3FFFFFFFu) : 0;
                    exc += __reduce_add_sync(0xffffffffu, contrib);
                    break;
                } else {
                    exc += __reduce_add_sync(0xffffffffu, (int)(d & 0x3FFFFFFFu));
                    base_j -= 32;
                }
            }
            if (lane == 31) {
                atomicExch(&g_desc[arr][blk], (unsigned)(exc + blockAgg) | 0x80000000u);
                s_prefix = exc;
            }
        }
    }
    __syncthreads();
    int base = s_prefix;
    if (i < NN) {
        int ex = base + inc - v;
        rp[i] = ex; off[i] = ex;
        if (arr == 0) g_dis[i] = rsqrtf((float)v + 1.0f);
        if (i == NN - 1) rp[NN] = base + inc;
    }
}

__global__ void k_fill(const int* __restrict__ ei) {
    int i = blockIdx.x * blockDim.x + threadIdx.x;
    if (i < NE / 2) {
        int2 s = *(const int2*)&ei[2 * i];
        int2 d = *(const int2*)&ei[NE + 2 * i];
        int p0 = atomicAdd(&g_off_dst[d.x], 1); g_col_src[p0] = (unsigned short)s.x;
        int p1 = atomicAdd(&g_off_dst[d.y], 1); g_col_src[p1] = (unsigned short)s.y;
        int q0 = atomicAdd(&g_off_src[s.x], 1); g_col_dst[q0] = (unsigned short)d.x;
        int q1 = atomicAdd(&g_off_src[s.y], 1); g_col_dst[q1] = (unsigned short)d.y;
    }
}

// ---------------- tensor-core encoder (double-buffered): x fp32 -> fp16 @ WtE ----------------
__global__ void __launch_bounds__(128) k_mma_enc(
    const float* __restrict__ x, const float* __restrict__ b1v)
{
    __shared__ __half As[2][64 * 72];
    __shared__ __half Bs[4][64 * 72];

    int tid = threadIdx.x;
    int rowbase = blockIdx.x * 64;
    int w = tid >> 5, lane = tid & 31;
    int g = lane >> 2, tig = lane & 3;
    int m0 = w * 16;

    #pragma unroll
    for (int c = 0; c < 4; c++) {
        #pragma unroll
        for (int it = 0; it < 8; it++) {
            int i = tid + it * 128;
            int n = i >> 4;
            int c4 = (i & 15) * 4;
            *(uint2*)&Bs[c][n * 72 + c4] = *(const uint2*)&g_WtE[n * 256 + c * 64 + c4];
        }
    }

    float c1[8][4];
    #pragma unroll
    for (int nc = 0; nc < 8; nc++)
        #pragma unroll
        for (int q = 0; q < 4; q++) c1[nc][q] = 0.f;

    float4 rg[8];
    #pragma unroll
    for (int it = 0; it < 8; it++) {
        int i = tid + it * 128;
        int row = rowbase + (i >> 4);
        int c4 = (i & 15) * 4;
        rg[it] = make_float4(0.f, 0.f, 0.f, 0.f);
        if (row < NN) rg[it] = *(const float4*)&x[(size_t)row * 256 + c4];
    }

    int buf = 0;
    #pragma unroll
    for (int c = 0; c < 4; c++) {
        #pragma unroll
        for (int it = 0; it < 8; it++) {
            int i = tid + it * 128;
            int r = i >> 4;
            int c4 = (i & 15) * 4;
            *(uint2*)&As[buf][r * 72 + c4] = f4_to_h4(rg[it]);
        }
        __syncthreads();
        if (c < 3) {
            #pragma unroll
            for (int it = 0; it < 8; it++) {
                int i = tid + it * 128;
                int row = rowbase + (i >> 4);
                int c4 = (i & 15) * 4;
                rg[it] = make_float4(0.f, 0.f, 0.f, 0.f);
                if (row < NN) rg[it] = *(const float4*)&x[(size_t)row * 256 + (c + 1) * 64 + c4];
            }
        }
        #pragma unroll
        for (int kc = 0; kc < 4; kc++) {
            int k0 = kc * 16 + tig * 2;
            unsigned a0 = *(const unsigned*)&As[buf][(m0 + g    ) * 72 + k0];
            unsigned a1 = *(const unsigned*)&As[buf][(m0 + g + 8) * 72 + k0];
            unsigned a2 = *(const unsigned*)&As[buf][(m0 + g    ) * 72 + k0 + 8];
            unsigned a3 = *(const unsigned*)&As[buf][(m0 + g + 8) * 72 + k0 + 8];
            #pragma unroll
            for (int nc = 0; nc < 8; nc++) {
                int nr = nc * 8 + g;
                unsigned p0 = *(const unsigned*)&Bs[c][nr * 72 + k0];
                unsigned p1 = *(const unsigned*)&Bs[c][nr * 72 + k0 + 8];
                mma16816(c1[nc], a0, a1, a2, a3, p0, p1);
            }
        }
        buf ^= 1;
    }

    int row_lo = rowbase + m0 + g;
    int row_hi = row_lo + 8;
    float dlo = (row_lo < NN) ? g_dis[row_lo] : 0.f;
    float dhi = (row_hi < NN) ? g_dis[row_hi] : 0.f;
    #pragma unroll
    for (int nc = 0; nc < 8; nc++) {
        int col = nc * 8 + tig * 2;
        float2 bb1 = *(const float2*)&b1v[col];
        if (row_lo < NN) {
            float2 o;
            o.x = fmaxf(c1[nc][0] + bb1.x, 0.f);
            o.y = fmaxf(c1[nc][1] + bb1.y, 0.f);
            *(float2*)&g_X[(size_t)row_lo * 64 + col] = o;
            *(__half2*)&g_XdH[(size_t)row_lo * 64 + col] =
                __floats2half2_rn(dlo * o.x, dlo * o.y);
        }
        if (row_hi < NN) {
            float2 o;
            o.x = fmaxf(c1[nc][2] + bb1.x, 0.f);
            o.y = fmaxf(c1[nc][3] + bb1.y, 0.f);
            *(float2*)&g_X[(size_t)row_hi * 64 + col] = o;
            *(__half2*)&g_XdH[(size_t)row_hi * 64 + col] =
                __floats2half2_rn(dhi * o.x, dhi * o.y);
        }
    }
}

// ---------------- tensor-core decoder: X[n x 64] fp32 -> fp16 @ WtD ----------------
__global__ void __launch_bounds__(128) k_mma_dec(
    const float* __restrict__ Xin, const float* __restrict__ b1v,
    float* __restrict__ out)
{
    __shared__ __half As[64 * 72];
    __shared__ __half Bs[64 * 72];

    int tid = threadIdx.x;
    int rowbase = blockIdx.x * 64;

    #pragma unroll
    for (int it = 0; it < 8; it++) {
        int i = tid + it * 128;
        int r = i >> 4;
        int c4 = (i & 15) * 4;
        int row = rowbase + r;
        float4 v = make_float4(0.f, 0.f, 0.f, 0.f);
        if (row < NN)
            v = *(const float4*)&Xin[(size_t)row * 64 + c4];
        *(uint2*)&As[r * 72 + c4] = f4_to_h4(v);
    }
    #pragma unroll
    for (int it = 0; it < 8; it++) {
        int i = tid + it * 128;
        int n = i >> 4;
        int c4 = (i & 15) * 4;
        *(uint2*)&Bs[n * 72 + c4] = *(const uint2*)&g_WtD[n * 64 + c4];
    }
    __syncthreads();

    int w = tid >> 5, lane = tid & 31;
    int g = lane >> 2, tig = lane & 3;
    int m0 = w * 16;

    float c1[8][4];
    #pragma unroll
    for (int nc = 0; nc < 8; nc++)
        #pragma unroll
        for (int q = 0; q < 4; q++) c1[nc][q] = 0.f;

    #pragma unroll
    for (int kc = 0; kc < 4; kc++) {
        int k0 = kc * 16 + tig * 2;
        unsigned a0 = *(const unsigned*)&As[(m0 + g    ) * 72 + k0];
        unsigned a1 = *(const unsigned*)&As[(m0 + g + 8) * 72 + k0];
        unsigned a2 = *(const unsigned*)&As[(m0 + g    ) * 72 + k0 + 8];
        unsigned a3 = *(const unsigned*)&As[(m0 + g + 8) * 72 + k0 + 8];
        #pragma unroll
        for (int nc = 0; nc < 8; nc++) {
            int nr = nc * 8 + g;
            unsigned p0 = *(const unsigned*)&Bs[nr * 72 + k0];
            unsigned p1 = *(const unsigned*)&Bs[nr * 72 + k0 + 8];
            mma16816(c1[nc], a0, a1, a2, a3, p0, p1);
        }
    }

    int row_lo = rowbase + m0 + g;
    int row_hi = row_lo + 8;
    #pragma unroll
    for (int nc = 0; nc < 8; nc++) {
        int col = nc * 8 + tig * 2;
        float2 bb1 = *(const float2*)&b1v[col];
        if (row_lo < NN) {
            float2 o;
            o.x = fmaxf(c1[nc][0] + bb1.x, 0.f);
            o.y = fmaxf(c1[nc][1] + bb1.y, 0.f);
            *(float2*)&out[(size_t)row_lo * 64 + col] = o;
        }
        if (row_hi < NN) {
            float2 o;
            o.x = fmaxf(c1[nc][2] + bb1.x, 0.f);
            o.y = fmaxf(c1[nc][3] + bb1.y, 0.f);
            *(float2*)&out[(size_t)row_hi * 64 + col] = o;
        }
    }
}

// ---------------- tensor-core dual GEMM: AH[n x 64] fp16 @ {Wt1,Wt2} ----------------
__global__ void __launch_bounds__(128) k_mma_dual(
    const float* __restrict__ b1v, const float* __restrict__ b2v)
{
    __shared__ __half As [64 * 72];
    __shared__ __half B1s[64 * 72];
    __shared__ __half B2s[64 * 72];

    int tid = threadIdx.x;
    int rowbase = blockIdx.x * 64;

    #pragma unroll
    for (int it = 0; it < 8; it++) {
        int i = tid + it * 128;
        int r = i >> 4;
        int c4 = (i & 15) * 4;
        int row = rowbase + r;
        uint2 v = make_uint2(0u, 0u);
        if (row < NN) v = *(const uint2*)&g_AH[(size_t)row * 64 + c4];
        *(uint2*)&As[r * 72 + c4] = v;
    }
    #pragma unroll
    for (int it = 0; it < 8; it++) {
        int i = tid + it * 128;
        int n = i >> 4;
        int c4 = (i & 15) * 4;
        *(uint2*)&B1s[n * 72 + c4] = *(const uint2*)&g_Wt1[n * 64 + c4];
        *(uint2*)&B2s[n * 72 + c4] = *(const uint2*)&g_Wt2[n * 64 + c4];
    }
    __syncthreads();

    int w = tid >> 5, lane = tid & 31;
    int g = lane >> 2, tig = lane & 3;
    int m0 = w * 16;

    float c1[8][4], c2[8][4];
    #pragma unroll
    for (int nc = 0; nc < 8; nc++)
        #pragma unroll
        for (int q = 0; q < 4; q++) { c1[nc][q] = 0.f; c2[nc][q] = 0.f; }

    #pragma unroll
    for (int kc = 0; kc < 4; kc++) {
        int k0 = kc * 16 + tig * 2;
        unsigned a0 = *(const unsigned*)&As[(m0 + g    ) * 72 + k0];
        unsigned a1 = *(const unsigned*)&As[(m0 + g + 8) * 72 + k0];
        unsigned a2 = *(const unsigned*)&As[(m0 + g    ) * 72 + k0 + 8];
        unsigned a3 = *(const unsigned*)&As[(m0 + g + 8) * 72 + k0 + 8];
        #pragma unroll
        for (int nc = 0; nc < 8; nc++) {
            int nr = nc * 8 + g;
            unsigned p0 = *(const unsigned*)&B1s[nr * 72 + k0];
            unsigned p1 = *(const unsigned*)&B1s[nr * 72 + k0 + 8];
            mma16816(c1[nc], a0, a1, a2, a3, p0, p1);
            unsigned q0 = *(const unsigned*)&B2s[nr * 72 + k0];
            unsigned q1 = *(const unsigned*)&B2s[nr * 72 + k0 + 8];
            mma16816(c2[nc], a0, a1, a2, a3, q0, q1);
        }
    }

    int row_lo = rowbase + m0 + g;
    int row_hi = row_lo + 8;
    #pragma unroll
    for (int nc = 0; nc < 8; nc++) {
        int col = nc * 8 + tig * 2;
        float2 bb1 = *(const float2*)&b1v[col];
        float2 bb2 = *(const float2*)&b2v[col];
        if (row_lo < NN) {
            *(__half2*)&g_XnH[(size_t)row_lo * 64 + col] =
                __floats2half2_rn(fmaxf(c1[nc][0] + bb1.x, 0.f),
                                  fmaxf(c1[nc][1] + bb1.y, 0.f));
            *(__half2*)&g_XGH[(size_t)row_lo * 64 + col] =
                __floats2half2_rn(fmaxf(c2[nc][0] + bb2.x, 0.f),
                                  fmaxf(c2[nc][1] + bb2.y, 0.f));
        }
        if (row_hi < NN) {
            *(__half2*)&g_XnH[(size_t)row_hi * 64 + col] =
                __floats2half2_rn(fmaxf(c1[nc][2] + bb1.x, 0.f),
                                  fmaxf(c1[nc][3] + bb1.y, 0.f));
            *(__half2*)&g_XGH[(size_t)row_hi * 64 + col] =
                __floats2half2_rn(fmaxf(c2[nc][2] + bb2.x, 0.f),
                                  fmaxf(c2[nc][3] + bb2.y, 0.f));
        }
    }
}

// ---------------- shared aggregation over in-edges (CSR by dst) ----------------
__global__ void __launch_bounds__(256) k_agg()
{
    int g = (blockIdx.x * blockDim.x + threadIdx.x) >> 4;
    int l = threadIdx.x & 15;
    if (g >= NN) return;
    int o = l * 4;

    float4 a = h4_to_f4(*(const uint2*)&g_XdH[(size_t)g * 64 + o]);  // self-loop

    int b = g_rp_dst[g], e = g_rp_dst[g + 1];
    int j = b;
    for (; j + 4 <= e; j += 4) {
        int s0 = g_col_src[j + 0];
        int s1 = g_col_src[j + 1];
        int s2 = g_col_src[j + 2];
        int s3 = g_col_src[j + 3];
        uint2 r0 = *(const uint2*)&g_XdH[(size_t)s0 * 64 + o];
        uint2 r1 = *(const uint2*)&g_XdH[(size_t)s1 * 64 + o];
        uint2 r2 = *(const uint2*)&g_XdH[(size_t)s2 * 64 + o];
        uint2 r3 = *(const uint2*)&g_XdH[(size_t)s3 * 64 + o];
        float4 v0 = h4_to_f4(r0), v1 = h4_to_f4(r1);
        float4 v2 = h4_to_f4(r2), v3 = h4_to_f4(r3);
        a.x += (v0.x + v1.x) + (v2.x + v3.x);
        a.y += (v0.y + v1.y) + (v2.y + v3.y);
        a.z += (v0.z + v1.z) + (v2.z + v3.z);
        a.w += (v0.w + v1.w) + (v2.w + v3.w);
    }
    for (; j < e; j++) {
        int s = g_col_src[j];
        float4 v = h4_to_f4(*(const uint2*)&g_XdH[(size_t)s * 64 + o]);
        a.x += v.x; a.y += v.y; a.z += v.z; a.w += v.w;
    }
    float d = g_dis[g];
    float4 r = make_float4(d * a.x, d * a.y, d * a.z, d * a.w);
    *(uint2*)&g_AH[(size_t)g * 64 + o] = f4_to_h4(r);
}

// ---------------- gate + state update (CSR by src) ----------------
__global__ void __launch_bounds__(256) k_gate()
{
    int g = (blockIdx.x * blockDim.x + threadIdx.x) >> 4;
    int l = threadIdx.x & 15;
    if (g >= NN) return;
    int o = l * 4;

    float4 xs = h4_to_f4(*(const uint2*)&g_XGH[(size_t)g * 64 + o]);
    float4 s = make_float4(0.f, 0.f, 0.f, 0.f);
    int b = g_rp_src[g], e = g_rp_src[g + 1];
    int j = b;
    for (; j + 4 <= e; j += 4) {
        int d0 = g_col_dst[j + 0];
        int d1 = g_col_dst[j + 1];
        int d2 = g_col_dst[j + 2];
        int d3 = g_col_dst[j + 3];
        uint2 r0 = *(const uint2*)&g_XGH[(size_t)d0 * 64 + o];
        uint2 r1 = *(const uint2*)&g_XGH[(size_t)d1 * 64 + o];
        uint2 r2 = *(const uint2*)&g_XGH[(size_t)d2 * 64 + o];
        uint2 r3 = *(const uint2*)&g_XGH[(size_t)d3 * 64 + o];
        float4 v0 = h4_to_f4(r0), v1 = h4_to_f4(r1);
        float4 v2 = h4_to_f4(r2), v3 = h4_to_f4(r3);
        float t;
        t = xs.x - v0.x; s.x += t * t;  t = xs.y - v0.y; s.y += t * t;
        t = xs.z - v0.z; s.z += t * t;  t = xs.w - v0.w; s.w += t * t;
        t = xs.x - v1.x; s.x += t * t;  t = xs.y - v1.y; s.y += t * t;
        t = xs.z - v1.z; s.z += t * t;  t = xs.w - v1.w; s.w += t * t;
        t = xs.x - v2.x; s.x += t * t;  t = xs.y - v2.y; s.y += t * t;
        t = xs.z - v2.z; s.z += t * t;  t = xs.w - v2.w; s.w += t * t;
        t = xs.x - v3.x; s.x += t * t;  t = xs.y - v3.y; s.y += t * t;
        t = xs.z - v3.z; s.z += t * t;  t = xs.w - v3.w; s.w += t * t;
    }
    for (; j < e; j++) {
        int d = g_col_dst[j];
        float4 v = h4_to_f4(*(const uint2*)&g_XGH[(size_t)d * 64 + o]);
        float t;
        t = xs.x - v.x; s.x += t * t;  t = xs.y - v.y; s.y += t * t;
        t = xs.z - v.z; s.z += t * t;  t = xs.w - v.w; s.w += t * t;
    }
    float inv = 1.0f / fmaxf((float)(e - b), 1.f);
    float4 tau;
    tau.x = tanhf(s.x * inv); tau.y = tanhf(s.y * inv);
    tau.z = tanhf(s.z * inv); tau.w = tanhf(s.w * inv);

    float4 xo = *(const float4*)&g_X [(size_t)g * 64 + o];
    float4 xn = h4_to_f4(*(const uint2*)&g_XnH[(size_t)g * 64 + o]);
    float4 r;
    r.x = xo.x + tau.x * (xn.x - xo.x);
    r.y = xo.y + tau.y * (xn.y - xo.y);
    r.z = xo.z + tau.z * (xn.z - xo.z);
    r.w = xo.w + tau.w * (xn.w - xo.w);
    *(float4*)&g_X[(size_t)g * 64 + o] = r;
    float di = g_dis[g];
    float4 rd = make_float4(di * r.x, di * r.y, di * r.z, di * r.w);
    *(uint2*)&g_XdH[(size_t)g * 64 + o] = f4_to_h4(rd);
}

// ---------------- launch ----------------
extern "C" void kernel_launch(void* const* d_in, const int* in_sizes, int n_in,
                              void* d_out, int out_size)
{
    const float* x      = (const float*)d_in[0];
    const int*   ei     = (const int*)  d_in[1];
    const float* enc_w  = (const float*)d_in[2];
    const float* enc_b  = (const float*)d_in[3];
    const float* conv_w = (const float*)d_in[4];
    const float* conv_b = (const float*)d_in[5];
    const float* gg_w   = (const float*)d_in[6];
    const float* gg_b   = (const float*)d_in[7];
    const float* dec_w  = (const float*)d_in[8];
    const float* dec_b  = (const float*)d_in[9];
    float* out = (float*)d_out;

    float *pX;
    cudaGetSymbolAddress((void**)&pX, g_X);

    const int MMA_BLOCKS  = (NN + 63) / 64;
    const int NODE_BLOCKS = (NN * 16 + 255) / 256;

    // preprocessing chain on the main (legacy) stream
    k_pre<<<NBLK, 256>>>(conv_w, gg_w, dec_w, enc_w);
    k_count<<<(NE / 2 + 255) / 256, 256>>>(ei);
    k_scan_one<<<dim3(NBLK, 2), 256>>>();

    // fork: encoder (needs dis from scan) runs on side stream,
    // overlapping k_fill on the main stream. Disjoint buffers — race-free.
    cudaEventRecord(g_ss.evFork, 0);
    cudaStreamWaitEvent(g_ss.s, g_ss.evFork, 0);
    k_mma_enc<<<MMA_BLOCKS, 128, 0, g_ss.s>>>(x, enc_b);
    cudaEventRecord(g_ss.evJoin, g_ss.s);

    k_fill<<<(NE / 2 + 255) / 256, 256>>>(ei);

    // join before the loop (needs both fill and encoder outputs)
    cudaStreamWaitEvent(0, g_ss.evJoin, 0);

    for (int it = 0; it < DEPTH; it++) {
        k_agg<<<NODE_BLOCKS, 256>>>();
        k_mma_dual<<<MMA_BLOCKS, 128>>>(conv_b, gg_b);
        k_gate<<<NODE_BLOCKS, 256>>>();
    }

    // decoder (tensor cores): out = relu(X @ dec_w + dec_b)
    k_mma_dec<<<MMA_BLOCKS, 128>>>(pX, dec_b, out);
}

// round 15
// speedup vs baseline: 1.0630x; 1.0630x over previous
#include <cuda_runtime.h>
#include <cuda_fp16.h>
#include <math.h>

#define NN 50000
#define NE 800000
#define DEPTH 4
#define NBLK 196   // (NN + 255) / 256

// ---------------- scratch (static device globals; no allocation) ----------------
__device__ float  g_X  [NN*64];   // node state (fp32)
__device__ __half g_XdH[NN*64];   // dis[i]*X[i] as fp16 (gather stream)
__device__ __half g_AH [NN*64];   // aggregated features as fp16 (MMA input)
__device__ __half g_XnH[NN*64];   // relu(conv(X)) as fp16
__device__ __half g_XGH[NN*64];   // relu(gate-conv(X)) as fp16 (gather stream)
__device__ __half g_Wt1[64*64];   // conv_w transposed fp16: [n][k]
__device__ __half g_Wt2[64*64];   // gg_w transposed fp16: [n][k]
__device__ __half g_WtD[64*64];   // dec_w transposed fp16: [n][k]
__device__ __half g_WtE[64*256];  // enc_w transposed fp16: [n][k]
__device__ float g_dis[NN];
__device__ int g_cnt_dst[NN];
__device__ int g_cnt_src[NN];
__device__ int g_rp_dst[NN+1];
__device__ int g_rp_src[NN+1];
__device__ int g_off_dst[NN];
__device__ int g_off_src[NN];
__device__ unsigned short g_col_src[NE];   // CSR by dst (16-bit node ids)
__device__ unsigned short g_col_dst[NE];   // CSR by src
__device__ unsigned g_desc[2][NBLK];       // decoupled-lookback descriptors

// ---------------- helpers ----------------
__device__ __forceinline__ float4 h4_to_f4(uint2 raw) {
    __half2 h0 = *reinterpret_cast<__half2*>(&raw.x);
    __half2 h1 = *reinterpret_cast<__half2*>(&raw.y);
    float2 f0 = __half22float2(h0);
    float2 f1 = __half22float2(h1);
    return make_float4(f0.x, f0.y, f1.x, f1.y);
}
__device__ __forceinline__ uint2 f4_to_h4(float4 v) {
    __half2 h0 = __floats2half2_rn(v.x, v.y);
    __half2 h1 = __floats2half2_rn(v.z, v.w);
    uint2 r;
    r.x = *reinterpret_cast<unsigned*>(&h0);
    r.y = *reinterpret_cast<unsigned*>(&h1);
    return r;
}
__device__ __forceinline__ void mma16816(float c[4],
    unsigned a0, unsigned a1, unsigned a2, unsigned a3,
    unsigned b0, unsigned b1)
{
    asm volatile(
        "mma.sync.aligned.m16n8k16.row.col.f32.f16.f16.f32 "
        "{%0,%1,%2,%3}, {%4,%5,%6,%7}, {%8,%9}, {%0,%1,%2,%3};"
        : "+f"(c[0]), "+f"(c[1]), "+f"(c[2]), "+f"(c[3])
        : "r"(a0), "r"(a1), "r"(a2), "r"(a3), "r"(b0), "r"(b1));
}

// inclusive block scan, 256 threads (8 warps)
__device__ __forceinline__ int block_incl_scan(int v, int* warpsums) {
    int lane = threadIdx.x & 31, wid = threadIdx.x >> 5;
    #pragma unroll
    for (int o = 1; o < 32; o <<= 1) {
        int u = __shfl_up_sync(0xffffffffu, v, o);
        if (lane >= o) v += u;
    }
    if (lane == 31) warpsums[wid] = v;
    __syncthreads();
    if (wid == 0) {
        int s = (lane < 8) ? warpsums[lane] : 0;
        #pragma unroll
        for (int o = 1; o < 8; o <<= 1) {
            int u = __shfl_up_sync(0xffffffffu, s, o);
            if (lane >= o) s += u;
        }
        if (lane < 8) warpsums[lane] = s;
    }
    __syncthreads();
    if (wid > 0) v += warpsums[wid - 1];
    return v;
}

// ---------------- prologue: zero counts/descriptors + convert weights ----------------
__global__ void k_pre(const float* __restrict__ w1, const float* __restrict__ w2,
                      const float* __restrict__ wd, const float* __restrict__ we) {
    int i = blockIdx.x * blockDim.x + threadIdx.x;
    if (i < NN) { g_cnt_dst[i] = 0; g_cnt_src[i] = 0; }
    if (i < NBLK) { g_desc[0][i] = 0u; g_desc[1][i] = 0u; }
    if (i < 4096) {
        int k = i >> 6, n = i & 63;
        g_Wt1[n * 64 + k] = __float2half(w1[i]);
        g_Wt2[n * 64 + k] = __float2half(w2[i]);
        g_WtD[n * 64 + k] = __float2half(wd[i]);
    }
    if (i < 16384) {
        int k = i >> 6, n = i & 63;
        g_WtE[n * 256 + k] = __float2half(we[i]);
    }
}

__global__ void k_count(const int* __restrict__ ei) {
    int i = blockIdx.x * blockDim.x + threadIdx.x;
    if (i < NE / 2) {
        int2 s = *(const int2*)&ei[2 * i];
        int2 d = *(const int2*)&ei[NE + 2 * i];
        atomicAdd(&g_cnt_dst[d.x], 1);
        atomicAdd(&g_cnt_dst[d.y], 1);
        atomicAdd(&g_cnt_src[s.x], 1);
        atomicAdd(&g_cnt_src[s.y], 1);
    }
}

// ---------------- single-pass scan with decoupled lookback ----------------
__global__ void __launch_bounds__(256) k_scan_one() {
    __shared__ int warpsums[8];
    __shared__ int s_prefix;
    int arr = blockIdx.y;
    const int* cnt = arr ? g_cnt_src : g_cnt_dst;
    int* rp  = arr ? g_rp_src  : g_rp_dst;
    int* off = arr ? g_off_src : g_off_dst;
    int blk = blockIdx.x;
    int i = blk * 256 + threadIdx.x;
    int v = (i < NN) ? cnt[i] : 0;
    int inc = block_incl_scan(v, warpsums);
    int lane = threadIdx.x & 31, wid = threadIdx.x >> 5;

    if (wid == 7) {
        int blockAgg = __shfl_sync(0xffffffffu, inc, 31);
        if (blk == 0) {
            if (lane == 31) {
                atomicExch(&g_desc[arr][0], (unsigned)blockAgg | 0x80000000u);
                s_prefix = 0;
            }
        } else {
            if (lane == 31)
                atomicExch(&g_desc[arr][blk], (unsigned)blockAgg | 0x40000000u);
            __syncwarp();
            int exc = 0;
            int base_j = blk - 1;
            while (true) {
                int j = base_j - (31 - lane);
                unsigned d;
                if (j >= 0) {
                    do { d = *((volatile unsigned*)&g_desc[arr][j]); }
                    while ((d & 0xC0000000u) == 0u);
                } else {
                    d = 0x80000000u;
                }
                unsigned pb = __ballot_sync(0xffffffffu, (d & 0x80000000u) != 0u);
                if (pb) {
                    int lp = 31 - __clz(pb);
                    int contrib = (lane >= lp) ? (int)(d & 0x3FFFFFFFu) : 0;
                    exc += __reduce_add_sync(0xffffffffu, contrib);
                    break;
                } else {
                    exc += __reduce_add_sync(0xffffffffu, (int)(d & 0x3FFFFFFFu));
                    base_j -= 32;
                }
            }
            if (lane == 31) {
                atomicExch(&g_desc[arr][blk], (unsigned)(exc + blockAgg) | 0x80000000u);
                s_prefix = exc;
            }
        }
    }
    __syncthreads();
    int base = s_prefix;
    if (i < NN) {
        int ex = base + inc - v;
        rp[i] = ex; off[i] = ex;
        if (arr == 0) g_dis[i] = rsqrtf((float)v + 1.0f);
        if (i == NN - 1) rp[NN] = base + inc;
    }
}

__global__ void k_fill(const int* __restrict__ ei) {
    int i = blockIdx.x * blockDim.x + threadIdx.x;
    if (i < NE / 2) {
        int2 s = *(const int2*)&ei[2 * i];
        int2 d = *(const int2*)&ei[NE + 2 * i];
        int p0 = atomicAdd(&g_off_dst[d.x], 1); g_col_src[p0] = (unsigned short)s.x;
        int p1 = atomicAdd(&g_off_dst[d.y], 1); g_col_src[p1] = (unsigned short)s.y;
        int q0 = atomicAdd(&g_off_src[s.x], 1); g_col_dst[q0] = (unsigned short)d.x;
        int q1 = atomicAdd(&g_off_src[s.y], 1); g_col_dst[q1] = (unsigned short)d.y;
    }
}

// ---------------- tensor-core encoder (double-buffered): x fp32 -> fp16 @ WtE ----------------
__global__ void __launch_bounds__(128) k_mma_enc(
    const float* __restrict__ x, const float* __restrict__ b1v)
{
    __shared__ __half As[2][64 * 72];
    __shared__ __half Bs[4][64 * 72];

    int tid = threadIdx.x;
    int rowbase = blockIdx.x * 64;
    int w = tid >> 5, lane = tid & 31;
    int g = lane >> 2, tig = lane & 3;
    int m0 = w * 16;

    #pragma unroll
    for (int c = 0; c < 4; c++) {
        #pragma unroll
        for (int it = 0; it < 8; it++) {
            int i = tid + it * 128;
            int n = i >> 4;
            int c4 = (i & 15) * 4;
            *(uint2*)&Bs[c][n * 72 + c4] = *(const uint2*)&g_WtE[n * 256 + c * 64 + c4];
        }
    }

    float c1[8][4];
    #pragma unroll
    for (int nc = 0; nc < 8; nc++)
        #pragma unroll
        for (int q = 0; q < 4; q++) c1[nc][q] = 0.f;

    float4 rg[8];
    #pragma unroll
    for (int it = 0; it < 8; it++) {
        int i = tid + it * 128;
        int row = rowbase + (i >> 4);
        int c4 = (i & 15) * 4;
        rg[it] = make_float4(0.f, 0.f, 0.f, 0.f);
        if (row < NN) rg[it] = *(const float4*)&x[(size_t)row * 256 + c4];
    }

    int buf = 0;
    #pragma unroll
    for (int c = 0; c < 4; c++) {
        #pragma unroll
        for (int it = 0; it < 8; it++) {
            int i = tid + it * 128;
            int r = i >> 4;
            int c4 = (i & 15) * 4;
            *(uint2*)&As[buf][r * 72 + c4] = f4_to_h4(rg[it]);
        }
        __syncthreads();
        if (c < 3) {
            #pragma unroll
            for (int it = 0; it < 8; it++) {
                int i = tid + it * 128;
                int row = rowbase + (i >> 4);
                int c4 = (i & 15) * 4;
                rg[it] = make_float4(0.f, 0.f, 0.f, 0.f);
                if (row < NN) rg[it] = *(const float4*)&x[(size_t)row * 256 + (c + 1) * 64 + c4];
            }
        }
        #pragma unroll
        for (int kc = 0; kc < 4; kc++) {
            int k0 = kc * 16 + tig * 2;
            unsigned a0 = *(const unsigned*)&As[buf][(m0 + g    ) * 72 + k0];
            unsigned a1 = *(const unsigned*)&As[buf][(m0 + g + 8) * 72 + k0];
            unsigned a2 = *(const unsigned*)&As[buf][(m0 + g    ) * 72 + k0 + 8];
            unsigned a3 = *(const unsigned*)&As[buf][(m0 + g + 8) * 72 + k0 + 8];
            #pragma unroll
            for (int nc = 0; nc < 8; nc++) {
                int nr = nc * 8 + g;
                unsigned p0 = *(const unsigned*)&Bs[c][nr * 72 + k0];
                unsigned p1 = *(const unsigned*)&Bs[c][nr * 72 + k0 + 8];
                mma16816(c1[nc], a0, a1, a2, a3, p0, p1);
            }
        }
        buf ^= 1;
    }

    int row_lo = rowbase + m0 + g;
    int row_hi = row_lo + 8;
    float dlo = (row_lo < NN) ? g_dis[row_lo] : 0.f;
    float dhi = (row_hi < NN) ? g_dis[row_hi] : 0.f;
    #pragma unroll
    for (int nc = 0; nc < 8; nc++) {
        int col = nc * 8 + tig * 2;
        float2 bb1 = *(const float2*)&b1v[col];
        if (row_lo < NN) {
            float2 o;
            o.x = fmaxf(c1[nc][0] + bb1.x, 0.f);
            o.y = fmaxf(c1[nc][1] + bb1.y, 0.f);
            *(float2*)&g_X[(size_t)row_lo * 64 + col] = o;
            *(__half2*)&g_XdH[(size_t)row_lo * 64 + col] =
                __floats2half2_rn(dlo * o.x, dlo * o.y);
        }
        if (row_hi < NN) {
            float2 o;
            o.x = fmaxf(c1[nc][2] + bb1.x, 0.f);
            o.y = fmaxf(c1[nc][3] + bb1.y, 0.f);
            *(float2*)&g_X[(size_t)row_hi * 64 + col] = o;
            *(__half2*)&g_XdH[(size_t)row_hi * 64 + col] =
                __floats2half2_rn(dhi * o.x, dhi * o.y);
        }
    }
}

// ---------------- tensor-core decoder (PDL): X[n x 64] fp32 -> fp16 @ WtD ----------------
__global__ void __launch_bounds__(128) k_mma_dec(
    const float* __restrict__ Xin, const float* __restrict__ b1v,
    float* __restrict__ out)
{
    __shared__ __half As[64 * 72];
    __shared__ __half Bs[64 * 72];

    int tid = threadIdx.x;
    int rowbase = blockIdx.x * 64;

    // predecessor-independent prologue: weight tile (written in preprocessing)
    #pragma unroll
    for (int it = 0; it < 8; it++) {
        int i = tid + it * 128;
        int n = i >> 4;
        int c4 = (i & 15) * 4;
        *(uint2*)&Bs[n * 72 + c4] = *(const uint2*)&g_WtD[n * 64 + c4];
    }

    cudaGridDependencySynchronize();   // wait for k_gate's g_X writes

    #pragma unroll
    for (int it = 0; it < 8; it++) {
        int i = tid + it * 128;
        int r = i >> 4;
        int c4 = (i & 15) * 4;
        int row = rowbase + r;
        float4 v = make_float4(0.f, 0.f, 0.f, 0.f);
        if (row < NN)
            v = *(const float4*)&Xin[(size_t)row * 64 + c4];
        *(uint2*)&As[r * 72 + c4] = f4_to_h4(v);
    }
    __syncthreads();

    int w = tid >> 5, lane = tid & 31;
    int g = lane >> 2, tig = lane & 3;
    int m0 = w * 16;

    float c1[8][4];
    #pragma unroll
    for (int nc = 0; nc < 8; nc++)
        #pragma unroll
        for (int q = 0; q < 4; q++) c1[nc][q] = 0.f;

    #pragma unroll
    for (int kc = 0; kc < 4; kc++) {
        int k0 = kc * 16 + tig * 2;
        unsigned a0 = *(const unsigned*)&As[(m0 + g    ) * 72 + k0];
        unsigned a1 = *(const unsigned*)&As[(m0 + g + 8) * 72 + k0];
        unsigned a2 = *(const unsigned*)&As[(m0 + g    ) * 72 + k0 + 8];
        unsigned a3 = *(const unsigned*)&As[(m0 + g + 8) * 72 + k0 + 8];
        #pragma unroll
        for (int nc = 0; nc < 8; nc++) {
            int nr = nc * 8 + g;
            unsigned p0 = *(const unsigned*)&Bs[nr * 72 + k0];
            unsigned p1 = *(const unsigned*)&Bs[nr * 72 + k0 + 8];
            mma16816(c1[nc], a0, a1, a2, a3, p0, p1);
        }
    }

    int row_lo = rowbase + m0 + g;
    int row_hi = row_lo + 8;
    #pragma unroll
    for (int nc = 0; nc < 8; nc++) {
        int col = nc * 8 + tig * 2;
        float2 bb1 = *(const float2*)&b1v[col];
        if (row_lo < NN) {
            float2 o;
            o.x = fmaxf(c1[nc][0] + bb1.x, 0.f);
            o.y = fmaxf(c1[nc][1] + bb1.y, 0.f);
            *(float2*)&out[(size_t)row_lo * 64 + col] = o;
        }
        if (row_hi < NN) {
            float2 o;
            o.x = fmaxf(c1[nc][2] + bb1.x, 0.f);
            o.y = fmaxf(c1[nc][3] + bb1.y, 0.f);
            *(float2*)&out[(size_t)row_hi * 64 + col] = o;
        }
    }
}

// ---------------- tensor-core dual GEMM (PDL): AH[n x 64] fp16 @ {Wt1,Wt2} ----------------
__global__ void __launch_bounds__(128) k_mma_dual(
    const float* __restrict__ b1v, const float* __restrict__ b2v)
{
    __shared__ __half As [64 * 72];
    __shared__ __half B1s[64 * 72];
    __shared__ __half B2s[64 * 72];

    int tid = threadIdx.x;
    int rowbase = blockIdx.x * 64;

    // predecessor-independent prologue: weight tiles
    #pragma unroll
    for (int it = 0; it < 8; it++) {
        int i = tid + it * 128;
        int n = i >> 4;
        int c4 = (i & 15) * 4;
        *(uint2*)&B1s[n * 72 + c4] = *(const uint2*)&g_Wt1[n * 64 + c4];
        *(uint2*)&B2s[n * 72 + c4] = *(const uint2*)&g_Wt2[n * 64 + c4];
    }

    cudaGridDependencySynchronize();   // wait for k_agg's g_AH writes

    #pragma unroll
    for (int it = 0; it < 8; it++) {
        int i = tid + it * 128;
        int r = i >> 4;
        int c4 = (i & 15) * 4;
        int row = rowbase + r;
        uint2 v = make_uint2(0u, 0u);
        if (row < NN) v = *(const uint2*)&g_AH[(size_t)row * 64 + c4];
        *(uint2*)&As[r * 72 + c4] = v;
    }
    __syncthreads();

    int w = tid >> 5, lane = tid & 31;
    int g = lane >> 2, tig = lane & 3;
    int m0 = w * 16;

    float c1[8][4], c2[8][4];
    #pragma unroll
    for (int nc = 0; nc < 8; nc++)
        #pragma unroll
        for (int q = 0; q < 4; q++) { c1[nc][q] = 0.f; c2[nc][q] = 0.f; }

    #pragma unroll
    for (int kc = 0; kc < 4; kc++) {
        int k0 = kc * 16 + tig * 2;
        unsigned a0 = *(const unsigned*)&As[(m0 + g    ) * 72 + k0];
        unsigned a1 = *(const unsigned*)&As[(m0 + g + 8) * 72 + k0];
        unsigned a2 = *(const unsigned*)&As[(m0 + g    ) * 72 + k0 + 8];
        unsigned a3 = *(const unsigned*)&As[(m0 + g + 8) * 72 + k0 + 8];
        #pragma unroll
        for (int nc = 0; nc < 8; nc++) {
            int nr = nc * 8 + g;
            unsigned p0 = *(const unsigned*)&B1s[nr * 72 + k0];
            unsigned p1 = *(const unsigned*)&B1s[nr * 72 + k0 + 8];
            mma16816(c1[nc], a0, a1, a2, a3, p0, p1);
            unsigned q0 = *(const unsigned*)&B2s[nr * 72 + k0];
            unsigned q1 = *(const unsigned*)&B2s[nr * 72 + k0 + 8];
            mma16816(c2[nc], a0, a1, a2, a3, q0, q1);
        }
    }

    int row_lo = rowbase + m0 + g;
    int row_hi = row_lo + 8;
    #pragma unroll
    for (int nc = 0; nc < 8; nc++) {
        int col = nc * 8 + tig * 2;
        float2 bb1 = *(const float2*)&b1v[col];
        float2 bb2 = *(const float2*)&b2v[col];
        if (row_lo < NN) {
            *(__half2*)&g_XnH[(size_t)row_lo * 64 + col] =
                __floats2half2_rn(fmaxf(c1[nc][0] + bb1.x, 0.f),
                                  fmaxf(c1[nc][1] + bb1.y, 0.f));
            *(__half2*)&g_XGH[(size_t)row_lo * 64 + col] =
                __floats2half2_rn(fmaxf(c2[nc][0] + bb2.x, 0.f),
                                  fmaxf(c2[nc][1] + bb2.y, 0.f));
        }
        if (row_hi < NN) {
            *(__half2*)&g_XnH[(size_t)row_hi * 64 + col] =
                __floats2half2_rn(fmaxf(c1[nc][2] + bb1.x, 0.f),
                                  fmaxf(c1[nc][3] + bb1.y, 0.f));
            *(__half2*)&g_XGH[(size_t)row_hi * 64 + col] =
                __floats2half2_rn(fmaxf(c2[nc][2] + bb2.x, 0.f),
                                  fmaxf(c2[nc][3] + bb2.y, 0.f));
        }
    }
}

// ---------------- shared aggregation over in-edges (PDL, CSR by dst) ----------------
__global__ void __launch_bounds__(256) k_agg()
{
    int g = (blockIdx.x * blockDim.x + threadIdx.x) >> 4;
    int l = threadIdx.x & 15;
    int o = l * 4;

    // predecessor-independent prologue: CSR row pointers + dis (preprocessing data)
    int b = 0, e = 0;
    float d = 0.f;
    if (g < NN) {
        b = g_rp_dst[g]; e = g_rp_dst[g + 1];
        d = g_dis[g];
    }

    cudaGridDependencySynchronize();   // wait for k_gate/k_mma_enc XdH writes
    if (g >= NN) return;

    float4 a = h4_to_f4(*(const uint2*)&g_XdH[(size_t)g * 64 + o]);  // self-loop

    int j = b;
    for (; j + 4 <= e; j += 4) {
        int s0 = g_col_src[j + 0];
        int s1 = g_col_src[j + 1];
        int s2 = g_col_src[j + 2];
        int s3 = g_col_src[j + 3];
        uint2 r0 = *(const uint2*)&g_XdH[(size_t)s0 * 64 + o];
        uint2 r1 = *(const uint2*)&g_XdH[(size_t)s1 * 64 + o];
        uint2 r2 = *(const uint2*)&g_XdH[(size_t)s2 * 64 + o];
        uint2 r3 = *(const uint2*)&g_XdH[(size_t)s3 * 64 + o];
        float4 v0 = h4_to_f4(r0), v1 = h4_to_f4(r1);
        float4 v2 = h4_to_f4(r2), v3 = h4_to_f4(r3);
        a.x += (v0.x + v1.x) + (v2.x + v3.x);
        a.y += (v0.y + v1.y) + (v2.y + v3.y);
        a.z += (v0.z + v1.z) + (v2.z + v3.z);
        a.w += (v0.w + v1.w) + (v2.w + v3.w);
    }
    for (; j < e; j++) {
        int s = g_col_src[j];
        float4 v = h4_to_f4(*(const uint2*)&g_XdH[(size_t)s * 64 + o]);
        a.x += v.x; a.y += v.y; a.z += v.z; a.w += v.w;
    }
    float4 r = make_float4(d * a.x, d * a.y, d * a.z, d * a.w);
    *(uint2*)&g_AH[(size_t)g * 64 + o] = f4_to_h4(r);
}

// ---------------- gate + state update (PDL, CSR by src) ----------------
__global__ void __launch_bounds__(256) k_gate()
{
    int g = (blockIdx.x * blockDim.x + threadIdx.x) >> 4;
    int l = threadIdx.x & 15;
    int o = l * 4;

    // predecessor-independent prologue
    int b = 0, e = 0;
    float di = 0.f;
    if (g < NN) {
        b = g_rp_src[g]; e = g_rp_src[g + 1];
        di = g_dis[g];
    }

    cudaGridDependencySynchronize();   // wait for k_mma_dual XGH/XnH writes
    if (g >= NN) return;

    float4 xs = h4_to_f4(*(const uint2*)&g_XGH[(size_t)g * 64 + o]);
    float4 s = make_float4(0.f, 0.f, 0.f, 0.f);
    int j = b;
    for (; j + 4 <= e; j += 4) {
        int d0 = g_col_dst[j + 0];
        int d1 = g_col_dst[j + 1];
        int d2 = g_col_dst[j + 2];
        int d3 = g_col_dst[j + 3];
        uint2 r0 = *(const uint2*)&g_XGH[(size_t)d0 * 64 + o];
        uint2 r1 = *(const uint2*)&g_XGH[(size_t)d1 * 64 + o];
        uint2 r2 = *(const uint2*)&g_XGH[(size_t)d2 * 64 + o];
        uint2 r3 = *(const uint2*)&g_XGH[(size_t)d3 * 64 + o];
        float4 v0 = h4_to_f4(r0), v1 = h4_to_f4(r1);
        float4 v2 = h4_to_f4(r2), v3 = h4_to_f4(r3);
        float t;
        t = xs.x - v0.x; s.x += t * t;  t = xs.y - v0.y; s.y += t * t;
        t = xs.z - v0.z; s.z += t * t;  t = xs.w - v0.w; s.w += t * t;
        t = xs.x - v1.x; s.x += t * t;  t = xs.y - v1.y; s.y += t * t;
        t = xs.z - v1.z; s.z += t * t;  t = xs.w - v1.w; s.w += t * t;
        t = xs.x - v2.x; s.x += t * t;  t = xs.y - v2.y; s.y += t * t;
        t = xs.z - v2.z; s.z += t * t;  t = xs.w - v2.w; s.w += t * t;
        t = xs.x - v3.x; s.x += t * t;  t = xs.y - v3.y; s.y += t * t;
        t = xs.z - v3.z; s.z += t * t;  t = xs.w - v3.w; s.w += t * t;
    }
    for (; j < e; j++) {
        int d = g_col_dst[j];
        float4 v = h4_to_f4(*(const uint2*)&g_XGH[(size_t)d * 64 + o]);
        float t;
        t = xs.x - v.x; s.x += t * t;  t = xs.y - v.y; s.y += t * t;
        t = xs.z - v.z; s.z += t * t;  t = xs.w - v.w; s.w += t * t;
    }
    float inv = 1.0f / fmaxf((float)(e - b), 1.f);
    float4 tau;
    tau.x = tanhf(s.x * inv); tau.y = tanhf(s.y * inv);
    tau.z = tanhf(s.z * inv); tau.w = tanhf(s.w * inv);

    float4 xo = *(const float4*)&g_X [(size_t)g * 64 + o];
    float4 xn = h4_to_f4(*(const uint2*)&g_XnH[(size_t)g * 64 + o]);
    float4 r;
    r.x = xo.x + tau.x * (xn.x - xo.x);
    r.y = xo.y + tau.y * (xn.y - xo.y);
    r.z = xo.z + tau.z * (xn.z - xo.z);
    r.w = xo.w + tau.w * (xn.w - xo.w);
    *(float4*)&g_X[(size_t)g * 64 + o] = r;
    float4 rd = make_float4(di * r.x, di * r.y, di * r.z, di * r.w);
    *(uint2*)&g_XdH[(size_t)g * 64 + o] = f4_to_h4(rd);
}

// ---------------- launch ----------------
extern "C" void kernel_launch(void* const* d_in, const int* in_sizes, int n_in,
                              void* d_out, int out_size)
{
    const float* x      = (const float*)d_in[0];
    const int*   ei     = (const int*)  d_in[1];
    const float* enc_w  = (const float*)d_in[2];
    const float* enc_b  = (const float*)d_in[3];
    const float* conv_w = (const float*)d_in[4];
    const float* conv_b = (const float*)d_in[5];
    const float* gg_w   = (const float*)d_in[6];
    const float* gg_b   = (const float*)d_in[7];
    const float* dec_w  = (const float*)d_in[8];
    const float* dec_b  = (const float*)d_in[9];
    float* out = (float*)d_out;

    float *pX;
    cudaGetSymbolAddress((void**)&pX, g_X);

    const int MMA_BLOCKS  = (NN + 63) / 64;
    const int NODE_BLOCKS = (NN * 16 + 255) / 256;

    // preprocessing chain (serial, single stream)
    k_pre<<<NBLK, 256>>>(conv_w, gg_w, dec_w, enc_w);
    k_count<<<(NE / 2 + 255) / 256, 256>>>(ei);
    k_scan_one<<<dim3(NBLK, 2), 256>>>();
    k_fill<<<(NE / 2 + 255) / 256, 256>>>(ei);

    // encoder (tensor cores, double-buffered)
    k_mma_enc<<<MMA_BLOCKS, 128>>>(x, enc_b);

    // PDL launch config: overlap each kernel's prologue with predecessor tail
    cudaLaunchAttribute pdlAttr[1];
    pdlAttr[0].id = cudaLaunchAttributeProgrammaticStreamSerialization;
    pdlAttr[0].val.programmaticStreamSerializationAllowed = 1;

    cudaLaunchConfig_t cfgNode = {};
    cfgNode.gridDim = dim3(NODE_BLOCKS);
    cfgNode.blockDim = dim3(256);
    cfgNode.attrs = pdlAttr;
    cfgNode.numAttrs = 1;

    cudaLaunchConfig_t cfgMma = {};
    cfgMma.gridDim = dim3(MMA_BLOCKS);
    cfgMma.blockDim = dim3(128);
    cfgMma.attrs = pdlAttr;
    cfgMma.numAttrs = 1;

    for (int it = 0; it < DEPTH; it++) {
        cudaLaunchKernelEx(&cfgNode, k_agg);
        cudaLaunchKernelEx(&cfgMma, k_mma_dual, conv_b, gg_b);
        cudaLaunchKernelEx(&cfgNode, k_gate);
    }

    // decoder (PDL)
    cudaLaunchKernelEx(&cfgMma, k_mma_dec, (const float*)pX, dec_b, out);
}